// round 1
// baseline (speedup 1.0000x reference)
#include <cuda_runtime.h>
#include <cuda_bf16.h>
#include <cstdint>

// BoltzmannRouter fused kernel (round 0: fp32 FFMA baseline)
//   scores = x @ gate_w^T / e ; softmax ; top-44 mask ; renormalize
// x: [N=16384, D=2048] f32, gate_w: [E=64, D=2048] f32, out: [N, 64] f32

#define D_DIM 2048
#define E_DIM 64
#define BT    64    // tokens per block
#define TK    32    // K-chunk
#define N_ACTIVE 44

__global__ __launch_bounds__(256, 2)
void boltzmann_router_kernel(const float* __restrict__ x,
                             const float* __restrict__ w,
                             float* __restrict__ out)
{
    __shared__ float xs[TK][BT];        // x tile, transposed [k][token]
    __shared__ float ws[TK][E_DIM];     // w tile, transposed [k][expert]
    __shared__ float scores[BT][E_DIM + 1];  // +1 pad

    const int tid  = threadIdx.x;
    const int tx   = tid & 15;          // token group  (16 groups of 4)
    const int ty   = tid >> 4;          // expert group (16 groups of 4)
    const int tok0 = blockIdx.x * BT;

    float acc[4][4];
    #pragma unroll
    for (int i = 0; i < 4; i++)
        #pragma unroll
        for (int j = 0; j < 4; j++) acc[i][j] = 0.0f;

    for (int k0 = 0; k0 < D_DIM; k0 += TK) {
        // ---- stage x tile: 64 tokens x 32 k, transposed into smem ----
        #pragma unroll
        for (int it = 0; it < 2; it++) {
            int f  = tid + it * 256;        // 0..511 float4 slots
            int t  = f >> 3;                // token 0..63
            int c4 = f & 7;                 // float4 within 32-k chunk
            float4 v = *reinterpret_cast<const float4*>(
                &x[(size_t)(tok0 + t) * D_DIM + k0 + c4 * 4]);
            xs[c4 * 4 + 0][t] = v.x;
            xs[c4 * 4 + 1][t] = v.y;
            xs[c4 * 4 + 2][t] = v.z;
            xs[c4 * 4 + 3][t] = v.w;
        }
        // ---- stage w tile: 64 experts x 32 k, transposed ----
        #pragma unroll
        for (int it = 0; it < 2; it++) {
            int f  = tid + it * 256;
            int e  = f >> 3;
            int c4 = f & 7;
            float4 v = *reinterpret_cast<const float4*>(
                &w[(size_t)e * D_DIM + k0 + c4 * 4]);
            ws[c4 * 4 + 0][e] = v.x;
            ws[c4 * 4 + 1][e] = v.y;
            ws[c4 * 4 + 2][e] = v.z;
            ws[c4 * 4 + 3][e] = v.w;
        }
        __syncthreads();

        #pragma unroll
        for (int k = 0; k < TK; k++) {
            float4 a = *reinterpret_cast<const float4*>(&xs[k][tx * 4]);
            float4 b = *reinterpret_cast<const float4*>(&ws[k][ty * 4]);
            acc[0][0] += a.x * b.x; acc[0][1] += a.x * b.y;
            acc[0][2] += a.x * b.z; acc[0][3] += a.x * b.w;
            acc[1][0] += a.y * b.x; acc[1][1] += a.y * b.y;
            acc[1][2] += a.y * b.z; acc[1][3] += a.y * b.w;
            acc[2][0] += a.z * b.x; acc[2][1] += a.z * b.y;
            acc[2][2] += a.z * b.z; acc[2][3] += a.z * b.w;
            acc[3][0] += a.w * b.x; acc[3][1] += a.w * b.y;
            acc[3][2] += a.w * b.z; acc[3][3] += a.w * b.w;
        }
        __syncthreads();
    }

    // ---- write scaled scores to smem (apply 1/temperature here) ----
    const float INV_TEMP = 0.36787944117144233f;  // 1/e
    #pragma unroll
    for (int i = 0; i < 4; i++)
        #pragma unroll
        for (int j = 0; j < 4; j++)
            scores[tx * 4 + i][ty * 4 + j] = acc[i][j] * INV_TEMP;
    __syncthreads();

    // ---- epilogue: one warp per 8 tokens ----
    const int warp = tid >> 5;
    const int lane = tid & 31;

    for (int tt = 0; tt < 8; tt++) {
        int t = warp * 8 + tt;
        float s0 = scores[t][lane];
        float s1 = scores[t][lane + 32];

        // softmax max
        float m = fmaxf(s0, s1);
        #pragma unroll
        for (int o = 16; o > 0; o >>= 1)
            m = fmaxf(m, __shfl_xor_sync(0xFFFFFFFFu, m, o));

        float e0 = __expf(s0 - m);
        float e1 = __expf(s1 - m);
        float z = e0 + e1;
        #pragma unroll
        for (int o = 16; o > 0; o >>= 1)
            z += __shfl_xor_sync(0xFFFFFFFFu, z, o);

        // rank = #{j : s_j > s_i, ties broken by lower index} (matches top_k)
        int c0 = 0, c1 = 0;
        #pragma unroll 16
        for (int j = 0; j < E_DIM; j++) {
            float sj = scores[t][j];
            c0 += (sj > s0) || (sj == s0 && j < lane);
            c1 += (sj > s1) || (sj == s1 && j < lane + 32);
        }
        bool keep0 = c0 < N_ACTIVE;
        bool keep1 = c1 < N_ACTIVE;

        float sk = (keep0 ? e0 : 0.0f) + (keep1 ? e1 : 0.0f);
        #pragma unroll
        for (int o = 16; o > 0; o >>= 1)
            sk += __shfl_xor_sync(0xFFFFFFFFu, sk, o);

        // weights = probs*mask / (sum(probs*mask) + eps)
        //         = e / (sk + eps * Z)
        float inv = 1.0f / (sk + 1e-8f * z);
        size_t base = (size_t)(tok0 + t) * E_DIM;
        out[base + lane]      = keep0 ? e0 * inv : 0.0f;
        out[base + lane + 32] = keep1 ? e1 * inv : 0.0f;
    }
}

extern "C" void kernel_launch(void* const* d_in, const int* in_sizes, int n_in,
                              void* d_out, int out_size)
{
    const float* x = (const float*)d_in[0];       // [N, 2048]
    const float* w = (const float*)d_in[1];       // [64, 2048]
    float* out     = (float*)d_out;               // [N, 64]
    int ntok = in_sizes[0] / D_DIM;               // 16384
    boltzmann_router_kernel<<<ntok / BT, 256>>>(x, w, out);
}

// round 3
// speedup vs baseline: 1.0734x; 1.0734x over previous
#include <cuda_runtime.h>
#include <cstdint>

// BoltzmannRouter fused kernel (round 1: packed f32x2 FFMA, smem-bound fix)
// x: [N=16384, D=2048] f32, gate_w: [64, D] f32, out: [N, 64] f32

#define D_DIM 2048
#define E_DIM 64
#define BT    128            // tokens per block
#define TK    16             // K-chunk
#define NCHUNK (D_DIM / TK)  // 128
#define N_ACTIVE 44
#define XS_STRIDE 132        // 128 + 4 pad (16B-aligned rows, conflict-free transpose)
#define WS_STRIDE 68         // 64 + 4 pad

#define FMA2(acc, a, b) \
    asm("fma.rn.f32x2 %0, %1, %2, %0;" : "+l"(acc) : "l"(a), "l"(b))

__global__ __launch_bounds__(256, 1)
void boltzmann_router_kernel(const float* __restrict__ x,
                             const float* __restrict__ w,
                             float* __restrict__ out)
{
    // GEMM tiles and the score buffer alias the same storage.
    __shared__ __align__(16) unsigned char smem_raw[BT * 65 * 4];  // 33280 B
    float* xs = (float*)smem_raw;                                  // [2][TK][XS_STRIDE]
    float* ws = (float*)(smem_raw + 2 * TK * XS_STRIDE * 4);       // [2][TK][WS_STRIDE]
    float* sc = (float*)smem_raw;                                  // [BT][65]

    const int tid  = threadIdx.x;
    const int tx   = tid & 15;     // token group (8 tokens)
    const int ty   = tid >> 4;     // expert group (4 experts)
    const int tok0 = blockIdx.x * BT;

    // acc2[e][tp]: expert ty*4+e, token pair (tx*8+2tp, tx*8+2tp+1)
    unsigned long long acc2[4][4];
    #pragma unroll
    for (int e = 0; e < 4; e++)
        #pragma unroll
        for (int p = 0; p < 4; p++) acc2[e][p] = 0ULL;

    // loader coords
    const int xt  = tid >> 2;      // token 0..63 (it adds 64)
    const int xc4 = tid & 3;       // which float4 within 16-k chunk
    const int we  = tid >> 2;      // expert 0..63
    const int wc4 = tid & 3;

    float4 rx0, rx1, rw;

    // ---- prefetch chunk 0 ----
    {
        const float* xb = x + (size_t)(tok0 + xt) * D_DIM + xc4 * 4;
        rx0 = *reinterpret_cast<const float4*>(xb);
        rx1 = *reinterpret_cast<const float4*>(xb + (size_t)64 * D_DIM);
        rw  = *reinterpret_cast<const float4*>(w + (size_t)we * D_DIM + wc4 * 4);
    }
    // ---- store chunk 0 into buffer 0 ----
    {
        float* xr = xs + (xc4 * 4) * XS_STRIDE;
        xr[0 * XS_STRIDE + xt] = rx0.x; xr[1 * XS_STRIDE + xt] = rx0.y;
        xr[2 * XS_STRIDE + xt] = rx0.z; xr[3 * XS_STRIDE + xt] = rx0.w;
        xr[0 * XS_STRIDE + 64 + xt] = rx1.x; xr[1 * XS_STRIDE + 64 + xt] = rx1.y;
        xr[2 * XS_STRIDE + 64 + xt] = rx1.z; xr[3 * XS_STRIDE + 64 + xt] = rx1.w;
        float* wr = ws + (wc4 * 4) * WS_STRIDE;
        wr[0 * WS_STRIDE + we] = rw.x; wr[1 * WS_STRIDE + we] = rw.y;
        wr[2 * WS_STRIDE + we] = rw.z; wr[3 * WS_STRIDE + we] = rw.w;
    }
    __syncthreads();

    for (int c = 0; c < NCHUNK; c++) {
        const int buf = c & 1;

        // prefetch chunk c+1 from global (overlaps with compute below)
        if (c + 1 < NCHUNK) {
            const float* xb = x + (size_t)(tok0 + xt) * D_DIM + (c + 1) * TK + xc4 * 4;
            rx0 = *reinterpret_cast<const float4*>(xb);
            rx1 = *reinterpret_cast<const float4*>(xb + (size_t)64 * D_DIM);
            rw  = *reinterpret_cast<const float4*>(
                      w + (size_t)we * D_DIM + (c + 1) * TK + wc4 * 4);
        }

        // ---- compute on buffer buf ----
        const float* xbase = xs + buf * TK * XS_STRIDE + tx * 8;
        const float* wbase = ws + buf * TK * WS_STRIDE + ty * 4;
        #pragma unroll
        for (int kk = 0; kk < TK; kk++) {
            ulonglong2 a01 = *reinterpret_cast<const ulonglong2*>(xbase + kk * XS_STRIDE);
            ulonglong2 a23 = *reinterpret_cast<const ulonglong2*>(xbase + kk * XS_STRIDE + 4);
            float4 bw = *reinterpret_cast<const float4*>(wbase + kk * WS_STRIDE);
            unsigned long long bb0, bb1, bb2, bb3;
            unsigned int u0 = __float_as_uint(bw.x), u1 = __float_as_uint(bw.y);
            unsigned int u2 = __float_as_uint(bw.z), u3 = __float_as_uint(bw.w);
            asm("mov.b64 %0, {%1, %1};" : "=l"(bb0) : "r"(u0));
            asm("mov.b64 %0, {%1, %1};" : "=l"(bb1) : "r"(u1));
            asm("mov.b64 %0, {%1, %1};" : "=l"(bb2) : "r"(u2));
            asm("mov.b64 %0, {%1, %1};" : "=l"(bb3) : "r"(u3));
            FMA2(acc2[0][0], a01.x, bb0); FMA2(acc2[0][1], a01.y, bb0);
            FMA2(acc2[0][2], a23.x, bb0); FMA2(acc2[0][3], a23.y, bb0);
            FMA2(acc2[1][0], a01.x, bb1); FMA2(acc2[1][1], a01.y, bb1);
            FMA2(acc2[1][2], a23.x, bb1); FMA2(acc2[1][3], a23.y, bb1);
            FMA2(acc2[2][0], a01.x, bb2); FMA2(acc2[2][1], a01.y, bb2);
            FMA2(acc2[2][2], a23.x, bb2); FMA2(acc2[2][3], a23.y, bb2);
            FMA2(acc2[3][0], a01.x, bb3); FMA2(acc2[3][1], a01.y, bb3);
            FMA2(acc2[3][2], a23.x, bb3); FMA2(acc2[3][3], a23.y, bb3);
        }

        // ---- store chunk c+1 into other buffer ----
        if (c + 1 < NCHUNK) {
            // safe without a pre-sync: previous readers of buf^1 finished
            // before the sync that ended iteration c-1.
            float* xr = xs + (buf ^ 1) * TK * XS_STRIDE + (xc4 * 4) * XS_STRIDE;
            xr[0 * XS_STRIDE + xt] = rx0.x; xr[1 * XS_STRIDE + xt] = rx0.y;
            xr[2 * XS_STRIDE + xt] = rx0.z; xr[3 * XS_STRIDE + xt] = rx0.w;
            xr[0 * XS_STRIDE + 64 + xt] = rx1.x; xr[1 * XS_STRIDE + 64 + xt] = rx1.y;
            xr[2 * XS_STRIDE + 64 + xt] = rx1.z; xr[3 * XS_STRIDE + 64 + xt] = rx1.w;
            float* wr = ws + (buf ^ 1) * TK * WS_STRIDE + (wc4 * 4) * WS_STRIDE;
            wr[0 * WS_STRIDE + we] = rw.x; wr[1 * WS_STRIDE + we] = rw.y;
            wr[2 * WS_STRIDE + we] = rw.z; wr[3 * WS_STRIDE + we] = rw.w;
            __syncthreads();
        }
    }

    // ---- all compute done; overwrite aliased smem with scaled scores ----
    __syncthreads();
    const float INV_TEMP = 0.36787944117144233f;  // 1/e
    #pragma unroll
    for (int e = 0; e < 4; e++) {
        #pragma unroll
        for (int p = 0; p < 4; p++) {
            unsigned int lo = (unsigned int)(acc2[e][p]);
            unsigned int hi = (unsigned int)(acc2[e][p] >> 32);
            int t0 = tx * 8 + 2 * p;
            int ec = ty * 4 + e;
            sc[t0 * 65 + ec]       = __uint_as_float(lo) * INV_TEMP;
            sc[(t0 + 1) * 65 + ec] = __uint_as_float(hi) * INV_TEMP;
        }
    }
    __syncthreads();

    // ---- epilogue: one warp per 16 tokens ----
    const int warp = tid >> 5;
    const int lane = tid & 31;

    for (int tt = 0; tt < 16; tt++) {
        int t = warp * 16 + tt;
        float s0 = sc[t * 65 + lane];
        float s1 = sc[t * 65 + 32 + lane];

        float m = fmaxf(s0, s1);
        #pragma unroll
        for (int o = 16; o > 0; o >>= 1)
            m = fmaxf(m, __shfl_xor_sync(0xFFFFFFFFu, m, o));

        float e0 = __expf(s0 - m);
        float e1 = __expf(s1 - m);
        float z = e0 + e1;
        #pragma unroll
        for (int o = 16; o > 0; o >>= 1)
            z += __shfl_xor_sync(0xFFFFFFFFu, z, o);

        // rank = #{j : s_j > s_i, ties broken by lower index}
        int c0 = 0, c1 = 0;
        #pragma unroll 16
        for (int j = 0; j < E_DIM; j++) {
            float sj = sc[t * 65 + j];
            c0 += (sj > s0) || (sj == s0 && j < lane);
            c1 += (sj > s1) || (sj == s1 && j < lane + 32);
        }
        bool keep0 = c0 < N_ACTIVE;
        bool keep1 = c1 < N_ACTIVE;

        float sk = (keep0 ? e0 : 0.0f) + (keep1 ? e1 : 0.0f);
        #pragma unroll
        for (int o = 16; o > 0; o >>= 1)
            sk += __shfl_xor_sync(0xFFFFFFFFu, sk, o);

        float inv = 1.0f / (sk + 1e-8f * z);
        size_t base = (size_t)(tok0 + t) * E_DIM;
        out[base + lane]      = keep0 ? e0 * inv : 0.0f;
        out[base + lane + 32] = keep1 ? e1 * inv : 0.0f;
    }
}

extern "C" void kernel_launch(void* const* d_in, const int* in_sizes, int n_in,
                              void* d_out, int out_size)
{
    const float* x = (const float*)d_in[0];   // [N, 2048]
    const float* w = (const float*)d_in[1];   // [64, 2048]
    float* out     = (float*)d_out;           // [N, 64]
    int ntok = in_sizes[0] / D_DIM;           // 16384
    boltzmann_router_kernel<<<ntok / BT, 256>>>(x, w, out);
}

// round 4
// speedup vs baseline: 1.5758x; 1.4680x over previous
#include <cuda_runtime.h>
#include <cstdint>

// BoltzmannRouter fused kernel (round 3: broadcast-w layout, expert-paired FFMA2)
// x: [N=16384, D=2048] f32, gate_w: [64, D] f32, out: [N, 64] f32

#define D_DIM 2048
#define E_DIM 64
#define BT    128            // tokens per block
#define TK    16             // K-chunk
#define NCHUNK (D_DIM / TK)  // 128
#define N_ACTIVE 44
#define XS_STRIDE 132        // floats; 16B-aligned rows
#define WS_STRIDE 68
#define SC_STRIDE 66         // even -> u64-aligned score stores

#define FMA2(acc, a, b) \
    asm("fma.rn.f32x2 %0, %1, %2, %0;" : "+l"(acc) : "l"(a), "l"(b))
#define DUP64(d, s) \
    asm("mov.b64 %0, {%1, %1};" : "=l"(d) : "r"(__float_as_uint(s)))

__global__ __launch_bounds__(256, 1)
void boltzmann_router_kernel(const float* __restrict__ x,
                             const float* __restrict__ w,
                             float* __restrict__ out)
{
    // GEMM tiles and the score buffer alias the same storage (33792 B).
    __shared__ __align__(16) unsigned char smem_raw[BT * SC_STRIDE * 4];
    float* xs = (float*)smem_raw;                                // [2][TK][XS_STRIDE]
    float* ws = (float*)(smem_raw + 2 * TK * XS_STRIDE * 4);     // [2][TK][WS_STRIDE]
    float* sc = (float*)smem_raw;                                // [BT][SC_STRIDE]

    const int tid  = threadIdx.x;
    const int lane = tid & 31;
    const int warp = tid >> 5;          // 8 warps
    const int e0   = warp * 8;          // this warp's 8 experts
    const int tok0 = blockIdx.x * BT;

    // acc2[i][j]: token lane*4+i, expert pair (e0+2j, e0+2j+1)
    unsigned long long acc2[4][4];
    #pragma unroll
    for (int i = 0; i < 4; i++)
        #pragma unroll
        for (int j = 0; j < 4; j++) acc2[i][j] = 0ULL;

    // loader coords
    const int xt  = tid >> 2;      // token 0..63 (second load adds 64)
    const int xc4 = tid & 3;       // float4 index within 16-k chunk
    const int we  = tid >> 2;      // expert 0..63
    const int wc4 = tid & 3;

    float4 rx0, rx1, rw;

    // ---- prefetch chunk 0 ----
    {
        const float* xb = x + (size_t)(tok0 + xt) * D_DIM + xc4 * 4;
        rx0 = *reinterpret_cast<const float4*>(xb);
        rx1 = *reinterpret_cast<const float4*>(xb + (size_t)64 * D_DIM);
        rw  = *reinterpret_cast<const float4*>(w + (size_t)we * D_DIM + wc4 * 4);
    }
    // ---- store chunk 0 into buffer 0 (transposed) ----
    {
        float* xr = xs + (xc4 * 4) * XS_STRIDE;
        xr[0 * XS_STRIDE + xt] = rx0.x; xr[1 * XS_STRIDE + xt] = rx0.y;
        xr[2 * XS_STRIDE + xt] = rx0.z; xr[3 * XS_STRIDE + xt] = rx0.w;
        xr[0 * XS_STRIDE + 64 + xt] = rx1.x; xr[1 * XS_STRIDE + 64 + xt] = rx1.y;
        xr[2 * XS_STRIDE + 64 + xt] = rx1.z; xr[3 * XS_STRIDE + 64 + xt] = rx1.w;
        float* wr = ws + (wc4 * 4) * WS_STRIDE;
        wr[0 * WS_STRIDE + we] = rw.x; wr[1 * WS_STRIDE + we] = rw.y;
        wr[2 * WS_STRIDE + we] = rw.z; wr[3 * WS_STRIDE + we] = rw.w;
    }
    __syncthreads();

    for (int c = 0; c < NCHUNK; c++) {
        const int buf = c & 1;

        // prefetch chunk c+1 from global (overlaps compute)
        if (c + 1 < NCHUNK) {
            const float* xb = x + (size_t)(tok0 + xt) * D_DIM + (c + 1) * TK + xc4 * 4;
            rx0 = *reinterpret_cast<const float4*>(xb);
            rx1 = *reinterpret_cast<const float4*>(xb + (size_t)64 * D_DIM);
            rw  = *reinterpret_cast<const float4*>(
                      w + (size_t)we * D_DIM + (c + 1) * TK + wc4 * 4);
        }

        // ---- compute on buffer buf ----
        const float* xbase = xs + buf * TK * XS_STRIDE + lane * 4;
        const float* wbase = ws + buf * TK * WS_STRIDE + e0;
        #pragma unroll
        for (int kk = 0; kk < TK; kk++) {
            float4 xf = *reinterpret_cast<const float4*>(xbase + kk * XS_STRIDE);
            // warp-uniform (broadcast) load of this warp's 8 experts
            ulonglong2 wv = *reinterpret_cast<const ulonglong2*>(wbase + kk * WS_STRIDE);
            unsigned long long b0 = wv.x, b1 = wv.y;
            ulonglong2 wv2 = *reinterpret_cast<const ulonglong2*>(wbase + kk * WS_STRIDE + 4);
            unsigned long long b2 = wv2.x, b3 = wv2.y;
            unsigned long long a0, a1, a2, a3;
            DUP64(a0, xf.x); DUP64(a1, xf.y); DUP64(a2, xf.z); DUP64(a3, xf.w);
            FMA2(acc2[0][0], a0, b0); FMA2(acc2[0][1], a0, b1);
            FMA2(acc2[0][2], a0, b2); FMA2(acc2[0][3], a0, b3);
            FMA2(acc2[1][0], a1, b0); FMA2(acc2[1][1], a1, b1);
            FMA2(acc2[1][2], a1, b2); FMA2(acc2[1][3], a1, b3);
            FMA2(acc2[2][0], a2, b0); FMA2(acc2[2][1], a2, b1);
            FMA2(acc2[2][2], a2, b2); FMA2(acc2[2][3], a2, b3);
            FMA2(acc2[3][0], a3, b0); FMA2(acc2[3][1], a3, b1);
            FMA2(acc2[3][2], a3, b2); FMA2(acc2[3][3], a3, b3);
        }

        // ---- store chunk c+1 into other buffer ----
        if (c + 1 < NCHUNK) {
            // safe without a pre-sync: last readers of buf^1 finished before
            // the sync that ended iteration c-1.
            float* xr = xs + (buf ^ 1) * TK * XS_STRIDE + (xc4 * 4) * XS_STRIDE;
            xr[0 * XS_STRIDE + xt] = rx0.x; xr[1 * XS_STRIDE + xt] = rx0.y;
            xr[2 * XS_STRIDE + xt] = rx0.z; xr[3 * XS_STRIDE + xt] = rx0.w;
            xr[0 * XS_STRIDE + 64 + xt] = rx1.x; xr[1 * XS_STRIDE + 64 + xt] = rx1.y;
            xr[2 * XS_STRIDE + 64 + xt] = rx1.z; xr[3 * XS_STRIDE + 64 + xt] = rx1.w;
            float* wr = ws + (buf ^ 1) * TK * WS_STRIDE + (wc4 * 4) * WS_STRIDE;
            wr[0 * WS_STRIDE + we] = rw.x; wr[1 * WS_STRIDE + we] = rw.y;
            wr[2 * WS_STRIDE + we] = rw.z; wr[3 * WS_STRIDE + we] = rw.w;
            __syncthreads();
        }
    }

    // ---- all compute done; overwrite aliased smem with scaled scores ----
    __syncthreads();
    const float INV_TEMP = 0.36787944117144233f;  // 1/e
    #pragma unroll
    for (int i = 0; i < 4; i++) {
        int t = lane * 4 + i;
        #pragma unroll
        for (int j = 0; j < 4; j++) {
            // scale both packed floats, store as one u64
            unsigned int lo = (unsigned int)(acc2[i][j]);
            unsigned int hi = (unsigned int)(acc2[i][j] >> 32);
            float f0 = __uint_as_float(lo) * INV_TEMP;
            float f1 = __uint_as_float(hi) * INV_TEMP;
            sc[t * SC_STRIDE + e0 + 2 * j]     = f0;
            sc[t * SC_STRIDE + e0 + 2 * j + 1] = f1;
        }
    }
    __syncthreads();

    // ---- epilogue: one warp per 16 tokens ----
    for (int tt = 0; tt < 16; tt++) {
        int t = warp * 16 + tt;
        float s0 = sc[t * SC_STRIDE + lane];
        float s1 = sc[t * SC_STRIDE + 32 + lane];

        float m = fmaxf(s0, s1);
        #pragma unroll
        for (int o = 16; o > 0; o >>= 1)
            m = fmaxf(m, __shfl_xor_sync(0xFFFFFFFFu, m, o));

        float e0v = __expf(s0 - m);
        float e1v = __expf(s1 - m);
        float z = e0v + e1v;
        #pragma unroll
        for (int o = 16; o > 0; o >>= 1)
            z += __shfl_xor_sync(0xFFFFFFFFu, z, o);

        // rank = #{j : s_j > s_i, ties broken by lower index}
        int c0 = 0, c1 = 0;
        #pragma unroll 16
        for (int j = 0; j < E_DIM; j++) {
            float sj = sc[t * SC_STRIDE + j];
            c0 += (sj > s0) || (sj == s0 && j < lane);
            c1 += (sj > s1) || (sj == s1 && j < lane + 32);
        }
        bool keep0 = c0 < N_ACTIVE;
        bool keep1 = c1 < N_ACTIVE;

        float sk = (keep0 ? e0v : 0.0f) + (keep1 ? e1v : 0.0f);
        #pragma unroll
        for (int o = 16; o > 0; o >>= 1)
            sk += __shfl_xor_sync(0xFFFFFFFFu, sk, o);

        float inv = 1.0f / (sk + 1e-8f * z);
        size_t base = (size_t)(tok0 + t) * E_DIM;
        out[base + lane]      = keep0 ? e0v * inv : 0.0f;
        out[base + lane + 32] = keep1 ? e1v * inv : 0.0f;
    }
}

extern "C" void kernel_launch(void* const* d_in, const int* in_sizes, int n_in,
                              void* d_out, int out_size)
{
    const float* x = (const float*)d_in[0];   // [N, 2048]
    const float* w = (const float*)d_in[1];   // [64, 2048]
    float* out     = (float*)d_out;           // [N, 64]
    int ntok = in_sizes[0] / D_DIM;           // 16384
    boltzmann_router_kernel<<<ntok / BT, 256>>>(x, w, out);
}